// round 5
// baseline (speedup 1.0000x reference)
#include <cuda_runtime.h>
#include <cstdint>

#define T_LEN 2048
#define E_DIM 256
#define H_DIM 512
#define G4    2048   // 4*H
#define D2    1024   // 2*H
#define KK    48
#define START_T 45
#define END_T   46

// ---------------- device scratch (no allocation; __device__ globals) ----------------
__device__ __align__(128) float g_x[(size_t)T_LEN * E_DIM];        // embedded input
__device__ __align__(128) float g_G0[(size_t)T_LEN * G4];          // gate preacts, fwd dir
__device__ __align__(128) float g_G1[(size_t)T_LEN * G4];          // gate preacts, bwd dir
__device__ __align__(128) float g_H0[(size_t)T_LEN * D2];          // layer-0 output [t][fwd|bwd]
__device__ __align__(128) float g_H1[(size_t)T_LEN * D2];          // layer-1 output
__device__ __align__(128) unsigned long long g_Hx[2][2][2][H_DIM]; // [layer][dir][parity][slot]
__device__ __align__(128) float g_feats[T_LEN * KK];
__device__ __align__(128) float g_expF[T_LEN * KK];
__device__ float  g_rowmax[T_LEN];
__device__ double g_score;
__device__ double g_rmsum;

// ---------------- helpers ----------------
__device__ __forceinline__ unsigned long long ld_cg64(const unsigned long long* p) {
    unsigned long long v;
    asm volatile("ld.global.cg.b64 %0, [%1];" : "=l"(v) : "l"(p) : "memory");
    return v;
}
__device__ __forceinline__ void st_cg64(unsigned long long* p, unsigned long long v) {
    asm volatile("st.global.cg.b64 [%0], %1;" :: "l"(p), "l"(v) : "memory");
}

// ---------------- reset exchange buffers (tag=0, value=0.0f) ----------------
__global__ void reset_kernel() {
    unsigned long long* p = &g_Hx[0][0][0][0];
    int i = blockIdx.x * blockDim.x + threadIdx.x;   // 8 blocks * 256 = 2048
    p[i] = 0ull;
    p[i + 2048] = 0ull;
}

// ---------------- embedding gather ----------------
__global__ void gather_kernel(const int* __restrict__ tokens,
                              const float* __restrict__ embed) {
    int t = blockIdx.x;
    g_x[(size_t)t * E_DIM + threadIdx.x] =
        embed[(size_t)tokens[t] * E_DIM + threadIdx.x];
}

// ---------------- fp32 NT GEMM: C[m][n] = sum_k A[m][k]*B[n][k] + b1[n] + b2[n] ----
// A selected by asel (0: g_x, 1: g_H0); C by csel (0: g_G0, 1: g_G1)
#define GBM 128
#define GBN 128
#define GBK 8
__global__ __launch_bounds__(256) void gemm_nt(
    int asel, const float* __restrict__ B,
    const float* __restrict__ bias1, const float* __restrict__ bias2,
    int csel, int M, int N, int Kd)
{
    const float* A = asel ? g_H0 : g_x;
    float* C       = csel ? g_G1 : g_G0;

    __shared__ float As[GBK][GBM];
    __shared__ float Bs[GBK][GBN];
    int tid = threadIdx.x;
    int m0 = blockIdx.y * GBM, n0 = blockIdx.x * GBN;
    int tx = tid & 15, ty = tid >> 4;     // 16x16 threads, 8x8 microtile each
    int lr = tid >> 1;                    // 0..127 row of tile
    int lc = (tid & 1) * 4;               // 0 or 4 within BK

    float acc[8][8];
#pragma unroll
    for (int i = 0; i < 8; i++)
#pragma unroll
        for (int jj = 0; jj < 8; jj++) acc[i][jj] = 0.f;

    const float* Ap = A + (size_t)(m0 + lr) * Kd + lc;
    const float* Bp = B + (size_t)(n0 + lr) * Kd + lc;

    for (int k0 = 0; k0 < Kd; k0 += GBK) {
        float4 av = *(const float4*)(Ap + k0);
        float4 bv = *(const float4*)(Bp + k0);
        __syncthreads();
        As[lc + 0][lr] = av.x; As[lc + 1][lr] = av.y;
        As[lc + 2][lr] = av.z; As[lc + 3][lr] = av.w;
        Bs[lc + 0][lr] = bv.x; Bs[lc + 1][lr] = bv.y;
        Bs[lc + 2][lr] = bv.z; Bs[lc + 3][lr] = bv.w;
        __syncthreads();
#pragma unroll
        for (int k = 0; k < GBK; k++) {
            float ar[8], br[8];
#pragma unroll
            for (int i = 0; i < 8; i++)  ar[i]  = As[k][ty * 8 + i];
#pragma unroll
            for (int jj = 0; jj < 8; jj++) br[jj] = Bs[k][tx * 8 + jj];
#pragma unroll
            for (int i = 0; i < 8; i++)
#pragma unroll
                for (int jj = 0; jj < 8; jj++)
                    acc[i][jj] = fmaf(ar[i], br[jj], acc[i][jj]);
        }
    }
#pragma unroll
    for (int i = 0; i < 8; i++) {
        size_t m = (size_t)(m0 + ty * 8 + i);
#pragma unroll
        for (int jj = 0; jj < 8; jj++) {
            int n = n0 + tx * 8 + jj;
            C[m * N + n] = acc[i][jj] + bias1[n] + bias2[n];
        }
    }
}

// ---------------- persistent recurrent LSTM step kernel ----------------
// 128 CTAs: blockIdx/64 = direction, 8 warps/CTA, each warp owns one h output j.
// W_hh rows (i,f,g,o for j) live in registers: 4x16 floats per lane.
// h exchange: tagged 64-bit words in L2, parity double-buffered by step.
__global__ __launch_bounds__(256, 1) void lstm_rec(
    const float* __restrict__ Wf, const float* __restrict__ Wb, int layer)
{
    const int d    = blockIdx.x >> 6;
    const int b    = blockIdx.x & 63;
    const int tid  = threadIdx.x;
    const int warp = tid >> 5, lane = tid & 31;
    const int j    = b * 8 + warp;

    const float* G = d ? g_G1 : g_G0;
    const float* W = d ? Wb : Wf;
    float* Hout    = layer ? g_H1 : g_H0;
    unsigned long long (*HX)[H_DIM] = g_Hx[layer][d];

    __shared__ float sh_h[H_DIM];

    float w0[16], w1[16], w2[16], w3[16];
#pragma unroll
    for (int u = 0; u < 16; u++) {
        int k = lane + 32 * u;
        w0[u] = W[(size_t)(0 * H_DIM + j) * H_DIM + k];
        w1[u] = W[(size_t)(1 * H_DIM + j) * H_DIM + k];
        w2[u] = W[(size_t)(2 * H_DIM + j) * H_DIM + k];
        w3[u] = W[(size_t)(3 * H_DIM + j) * H_DIM + k];
    }
    float c = 0.f;

    for (int s = 1; s <= T_LEN; s++) {
        const int t = d ? (T_LEN - s) : (s - 1);
        const float* Gp = G + (size_t)t * G4 + j;
        float pi = Gp[0];
        float pf = Gp[H_DIM];
        float pg = Gp[2 * H_DIM];
        float po = Gp[3 * H_DIM];

        // gather previous h (tagged words, exact-tag match; parity buffer)
        const unsigned expect = (unsigned)(s - 1);
        const unsigned long long* src = HX[(s - 1) & 1];
#pragma unroll
        for (int r = 0; r < 2; r++) {
            int idx = tid + r * 256;
            unsigned long long v = ld_cg64(&src[idx]);
            while ((unsigned)(v >> 32) != expect) {
                __nanosleep(20);
                v = ld_cg64(&src[idx]);
            }
            sh_h[idx] = __uint_as_float((unsigned)v);
        }
        __syncthreads();

        // h @ W_hh^T for this warp's 4 gates
        float a0 = 0.f, a1 = 0.f, a2 = 0.f, a3 = 0.f;
#pragma unroll
        for (int u = 0; u < 16; u++) {
            float hv = sh_h[lane + 32 * u];
            a0 = fmaf(w0[u], hv, a0);
            a1 = fmaf(w1[u], hv, a1);
            a2 = fmaf(w2[u], hv, a2);
            a3 = fmaf(w3[u], hv, a3);
        }
#pragma unroll
        for (int off = 16; off; off >>= 1) {
            a0 += __shfl_xor_sync(0xffffffffu, a0, off);
            a1 += __shfl_xor_sync(0xffffffffu, a1, off);
            a2 += __shfl_xor_sync(0xffffffffu, a2, off);
            a3 += __shfl_xor_sync(0xffffffffu, a3, off);
        }
        float gi = pi + a0, gf = pf + a1, gg = pg + a2, go = po + a3;
        float ii = 1.f / (1.f + expf(-gi));
        float ff = 1.f / (1.f + expf(-gf));
        float cc = tanhf(gg);
        float oo = 1.f / (1.f + expf(-go));
        c = ff * c + ii * cc;
        float h = oo * tanhf(c);

        if (lane == 0) {
            Hout[(size_t)t * D2 + d * H_DIM + j] = h;
            unsigned long long pk =
                ((unsigned long long)(unsigned)s << 32) |
                (unsigned long long)__float_as_uint(h);
            st_cg64(&HX[s & 1][j], pk);
        }
        __syncthreads();  // protect sh_h against next-step overwrite
    }
}

// ---------------- features: feats = H1 @ lin_w^T + lin_b; expF = exp(f - rowmax) ----
__global__ __launch_bounds__(512) void feats_kernel(
    const float* __restrict__ lin_w, const float* __restrict__ lin_b)
{
    int t = blockIdx.x;
    int tid = threadIdx.x;
    int warp = tid >> 5, lane = tid & 31;
    __shared__ float sh[D2];
    __shared__ float pb[KK];
    __shared__ float mxs;
    for (int i = tid; i < D2; i += 512) sh[i] = g_H1[(size_t)t * D2 + i];
    __syncthreads();
#pragma unroll
    for (int q = 0; q < 3; q++) {
        int j = warp * 3 + q;   // 16 warps * 3 = 48
        float acc = 0.f;
        for (int k = lane; k < D2; k += 32)
            acc = fmaf(sh[k], lin_w[(size_t)j * D2 + k], acc);
#pragma unroll
        for (int off = 16; off; off >>= 1)
            acc += __shfl_xor_sync(0xffffffffu, acc, off);
        if (lane == 0) pb[j] = acc + lin_b[j];
    }
    __syncthreads();
    if (tid < 16) {
        float m = fmaxf(pb[tid], fmaxf(pb[tid + 16], pb[tid + 32]));
#pragma unroll
        for (int off = 8; off; off >>= 1)
            m = fmaxf(m, __shfl_xor_sync(0xffffu, m, off));
        if (tid == 0) { mxs = m; g_rowmax[t] = m; }
    }
    __syncthreads();
    if (tid < KK) {
        float f = pb[tid];
        g_feats[t * KK + tid] = f;
        g_expF[t * KK + tid]  = expf(f - mxs);
    }
}

// ---------------- gold score (+ rowmax sum), double precision ----------------
__global__ void score_kernel(const int* __restrict__ tags,
                             const float* __restrict__ trans)
{
    __shared__ double red[256];
    int tid = threadIdx.x;
    double part = 0.0, rm = 0.0;
    for (int s = tid; s < T_LEN; s += 256) {
        int prev = (s == 0) ? START_T : tags[s - 1];
        int cur  = tags[s];
        part += (double)trans[cur * KK + prev] + (double)g_feats[s * KK + cur];
        rm   += (double)g_rowmax[s];
    }
    red[tid] = part;
    __syncthreads();
    for (int off = 128; off; off >>= 1) {
        if (tid < off) red[tid] += red[tid + off];
        __syncthreads();
    }
    if (tid == 0)
        g_score = red[0] + (double)trans[END_T * KK + tags[T_LEN - 1]];
    __syncthreads();
    red[tid] = rm;
    __syncthreads();
    for (int off = 128; off; off >>= 1) {
        if (tid < off) red[tid] += red[tid + off];
        __syncthreads();
    }
    if (tid == 0) g_rmsum = red[0];
}

// ---------------- CRF forward scan (probability domain, single block) ----------
__global__ __launch_bounds__(192) void crf_kernel(
    const float* __restrict__ trans,
    const int* __restrict__ seq_len,
    float* __restrict__ out)
{
    __shared__ float E[KK * KK];
    __shared__ float a[KK];
    __shared__ float pb[KK];
    __shared__ float red[4][KK];
    __shared__ float scale_s;
    int tid = threadIdx.x;
    int j = tid % KK, grp = tid / KK;           // 4 groups x 48
    for (int idx = tid; idx < KK * KK; idx += 192) E[idx] = expf(trans[idx]);
    if (tid < KK) a[tid] = (tid == START_T) ? 1.f : 0.f;
    __syncthreads();

    double C = 0.0;
    for (int t = 0; t < T_LEN; t++) {
        float ef = (grp == 0) ? g_expF[t * KK + j] : 0.f;
        float part = 0.f;
        int base = grp * 12;
#pragma unroll
        for (int ii = 0; ii < 12; ii++)
            part = fmaf(a[base + ii], E[j * KK + base + ii], part);
        red[grp][j] = part;
        __syncthreads();
        if (grp == 0)
            pb[j] = (red[0][j] + red[1][j] + red[2][j] + red[3][j]) * ef;
        __syncthreads();
        if (tid < 16) {
            float m = fmaxf(pb[tid], fmaxf(pb[tid + 16], pb[tid + 32]));
#pragma unroll
            for (int off = 8; off; off >>= 1)
                m = fmaxf(m, __shfl_xor_sync(0xffffu, m, off));
            if (tid == 0) { scale_s = 1.f / m; C += (double)logf(m); }
        }
        __syncthreads();
        if (tid < KK) a[tid] = pb[tid] * scale_s;
        __syncthreads();
    }
    if (tid == 0) {
        double z = 0.0;
        for (int q = 0; q < KK; q++)
            z += (double)a[q] * exp((double)trans[END_T * KK + q]);
        double logZ = C + log(z) + g_rmsum;
        out[0] = (float)((logZ - g_score) / (double)seq_len[0]);
    }
}

// ---------------- launch ----------------
extern "C" void kernel_launch(void* const* d_in, const int* in_sizes, int n_in,
                              void* d_out, int out_size) {
    const int*   tokens     = (const int*)d_in[0];
    const int*   tags       = (const int*)d_in[1];
    const int*   seqlen     = (const int*)d_in[2];
    const float* embed      = (const float*)d_in[3];
    const float* w_ih_l0_f  = (const float*)d_in[4];
    const float* w_hh_l0_f  = (const float*)d_in[5];
    const float* b_ih_l0_f  = (const float*)d_in[6];
    const float* b_hh_l0_f  = (const float*)d_in[7];
    const float* w_ih_l0_b  = (const float*)d_in[8];
    const float* w_hh_l0_b  = (const float*)d_in[9];
    const float* b_ih_l0_b  = (const float*)d_in[10];
    const float* b_hh_l0_b  = (const float*)d_in[11];
    const float* w_ih_l1_f  = (const float*)d_in[12];
    const float* w_hh_l1_f  = (const float*)d_in[13];
    const float* b_ih_l1_f  = (const float*)d_in[14];
    const float* b_hh_l1_f  = (const float*)d_in[15];
    const float* w_ih_l1_b  = (const float*)d_in[16];
    const float* w_hh_l1_b  = (const float*)d_in[17];
    const float* b_ih_l1_b  = (const float*)d_in[18];
    const float* b_hh_l1_b  = (const float*)d_in[19];
    const float* lin_w      = (const float*)d_in[20];
    const float* lin_b      = (const float*)d_in[21];
    const float* trans      = (const float*)d_in[22];
    float* out = (float*)d_out;

    reset_kernel<<<8, 256>>>();
    gather_kernel<<<T_LEN, E_DIM>>>(tokens, embed);

    dim3 g16(G4 / GBN, T_LEN / GBM);
    // layer 0 input preactivations (Kd = E)
    gemm_nt<<<g16, 256>>>(0, w_ih_l0_f, b_ih_l0_f, b_hh_l0_f, 0, T_LEN, G4, E_DIM);
    gemm_nt<<<g16, 256>>>(0, w_ih_l0_b, b_ih_l0_b, b_hh_l0_b, 1, T_LEN, G4, E_DIM);
    lstm_rec<<<128, 256>>>(w_hh_l0_f, w_hh_l0_b, 0);

    // layer 1 input preactivations (Kd = 2H)
    gemm_nt<<<g16, 256>>>(1, w_ih_l1_f, b_ih_l1_f, b_hh_l1_f, 0, T_LEN, G4, D2);
    gemm_nt<<<g16, 256>>>(1, w_ih_l1_b, b_ih_l1_b, b_hh_l1_b, 1, T_LEN, G4, D2);
    lstm_rec<<<128, 256>>>(w_hh_l1_f, w_hh_l1_b, 1);

    feats_kernel<<<T_LEN, 512>>>(lin_w, lin_b);
    score_kernel<<<1, 256>>>(tags, trans);
    crf_kernel<<<1, 192>>>(trans, seqlen, out);
}

// round 6
// speedup vs baseline: 1.0946x; 1.0946x over previous
#include <cuda_runtime.h>
#include <cstdint>

#define T_LEN 2048
#define E_DIM 256
#define H_DIM 512
#define G4    2048   // 4*H
#define D2    1024   // 2*H
#define KK    48
#define START_T 45
#define END_T   46

// ---------------- device scratch (no allocation; __device__ globals) ----------------
__device__ __align__(128) float g_x[(size_t)T_LEN * E_DIM];        // embedded input
__device__ __align__(128) float g_G0[(size_t)T_LEN * G4];          // gate preacts, fwd dir
__device__ __align__(128) float g_G1[(size_t)T_LEN * G4];          // gate preacts, bwd dir
__device__ __align__(128) float g_H0[(size_t)T_LEN * D2];          // layer-0 output [t][fwd|bwd]
__device__ __align__(128) float g_H1[(size_t)T_LEN * D2];          // layer-1 output
__device__ __align__(128) unsigned long long g_Hx[2][2][2][H_DIM]; // [layer][dir][parity][slot]
__device__ __align__(128) float g_feats[T_LEN * KK];
__device__ __align__(128) float g_expF[T_LEN * KK];
__device__ float  g_rowmax[T_LEN];
__device__ double g_score;
__device__ double g_rmsum;

// ---------------- helpers ----------------
__device__ __forceinline__ unsigned long long ld_cg64(const unsigned long long* p) {
    unsigned long long v;
    asm volatile("ld.global.cg.b64 %0, [%1];" : "=l"(v) : "l"(p) : "memory");
    return v;
}
__device__ __forceinline__ void st_cg64(unsigned long long* p, unsigned long long v) {
    asm volatile("st.global.cg.b64 [%0], %1;" :: "l"(p), "l"(v) : "memory");
}

// Fast branch-free activations (MUFU ex2/rcp based, rel err ~1e-6).
// fsig: exp overflow -> inf -> 1/inf = 0 (correct limit); underflow -> 1 (correct).
__device__ __forceinline__ float fsig(float x) {
    float t = __expf(-x);
    return __fdividef(1.f, 1.f + t);
}
__device__ __forceinline__ float ftanh_(float x) {
    x = fminf(fmaxf(x, -15.f), 15.f);   // avoid inf/inf
    float t = __expf(2.f * x);
    return __fdividef(t - 1.f, t + 1.f);
}

// ---------------- reset exchange buffers (tag=0, value=0.0f) ----------------
__global__ void reset_kernel() {
    unsigned long long* p = &g_Hx[0][0][0][0];
    int i = blockIdx.x * blockDim.x + threadIdx.x;   // 8 blocks * 256 = 2048
    p[i] = 0ull;
    p[i + 2048] = 0ull;
}

// ---------------- embedding gather ----------------
__global__ void gather_kernel(const int* __restrict__ tokens,
                              const float* __restrict__ embed) {
    int t = blockIdx.x;
    g_x[(size_t)t * E_DIM + threadIdx.x] =
        embed[(size_t)tokens[t] * E_DIM + threadIdx.x];
}

// ---------------- fp32 NT GEMM: C[m][n] = sum_k A[m][k]*B[n][k] + b1[n] + b2[n] ----
// A selected by asel (0: g_x, 1: g_H0); C by csel (0: g_G0, 1: g_G1)
#define GBM 128
#define GBN 128
#define GBK 8
__global__ __launch_bounds__(256, 2) void gemm_nt(
    int asel, const float* __restrict__ B,
    const float* __restrict__ bias1, const float* __restrict__ bias2,
    int csel, int M, int N, int Kd)
{
    const float* A = asel ? g_H0 : g_x;
    float* C       = csel ? g_G1 : g_G0;

    __shared__ float As[GBK][GBM];
    __shared__ float Bs[GBK][GBN];
    int tid = threadIdx.x;
    int m0 = blockIdx.y * GBM, n0 = blockIdx.x * GBN;
    int tx = tid & 15, ty = tid >> 4;     // 16x16 threads, 8x8 microtile each
    int lr = tid >> 1;                    // 0..127 row of tile
    int lc = (tid & 1) * 4;               // 0 or 4 within BK

    float acc[8][8];
#pragma unroll
    for (int i = 0; i < 8; i++)
#pragma unroll
        for (int jj = 0; jj < 8; jj++) acc[i][jj] = 0.f;

    const float* Ap = A + (size_t)(m0 + lr) * Kd + lc;
    const float* Bp = B + (size_t)(n0 + lr) * Kd + lc;

    for (int k0 = 0; k0 < Kd; k0 += GBK) {
        float4 av = *(const float4*)(Ap + k0);
        float4 bv = *(const float4*)(Bp + k0);
        __syncthreads();
        As[lc + 0][lr] = av.x; As[lc + 1][lr] = av.y;
        As[lc + 2][lr] = av.z; As[lc + 3][lr] = av.w;
        Bs[lc + 0][lr] = bv.x; Bs[lc + 1][lr] = bv.y;
        Bs[lc + 2][lr] = bv.z; Bs[lc + 3][lr] = bv.w;
        __syncthreads();
#pragma unroll
        for (int k = 0; k < GBK; k++) {
            float ar[8], br[8];
#pragma unroll
            for (int i = 0; i < 8; i++)  ar[i]  = As[k][ty * 8 + i];
#pragma unroll
            for (int jj = 0; jj < 8; jj++) br[jj] = Bs[k][tx * 8 + jj];
#pragma unroll
            for (int i = 0; i < 8; i++)
#pragma unroll
                for (int jj = 0; jj < 8; jj++)
                    acc[i][jj] = fmaf(ar[i], br[jj], acc[i][jj]);
        }
    }
#pragma unroll
    for (int i = 0; i < 8; i++) {
        size_t m = (size_t)(m0 + ty * 8 + i);
#pragma unroll
        for (int jj = 0; jj < 8; jj++) {
            int n = n0 + tx * 8 + jj;
            C[m * N + n] = acc[i][jj] + bias1[n] + bias2[n];
        }
    }
}

// ---------------- persistent recurrent LSTM step kernel ----------------
// 128 CTAs: blockIdx/64 = direction, 8 warps/CTA, each warp owns one h output j.
// W_hh rows (i,f,g,o for j) live in registers: 4x16 floats per lane.
// h exchange: tagged 64-bit words in L2, parity double-buffered by step.
// sh_h parity double-buffered -> single __syncthreads per step.
__global__ __launch_bounds__(256, 1) void lstm_rec(
    const float* __restrict__ Wf, const float* __restrict__ Wb, int layer)
{
    const int d    = blockIdx.x >> 6;
    const int b    = blockIdx.x & 63;
    const int tid  = threadIdx.x;
    const int warp = tid >> 5, lane = tid & 31;
    const int j    = b * 8 + warp;

    const float* G = d ? g_G1 : g_G0;
    const float* W = d ? Wb : Wf;
    float* Hout    = layer ? g_H1 : g_H0;
    unsigned long long (*HX)[H_DIM] = g_Hx[layer][d];

    __shared__ float sh_h[2][H_DIM];

    float w0[16], w1[16], w2[16], w3[16];
#pragma unroll
    for (int u = 0; u < 16; u++) {
        int k = lane + 32 * u;
        w0[u] = W[(size_t)(0 * H_DIM + j) * H_DIM + k];
        w1[u] = W[(size_t)(1 * H_DIM + j) * H_DIM + k];
        w2[u] = W[(size_t)(2 * H_DIM + j) * H_DIM + k];
        w3[u] = W[(size_t)(3 * H_DIM + j) * H_DIM + k];
    }
    float c = 0.f;

    for (int s = 1; s <= T_LEN; s++) {
        const int t = d ? (T_LEN - s) : (s - 1);
        const int p = (s - 1) & 1;
        const float* Gp = G + (size_t)t * G4 + j;
        // issue G-preact loads early; they complete during the poll
        float pi = Gp[0];
        float pf = Gp[H_DIM];
        float pg = Gp[2 * H_DIM];
        float po = Gp[3 * H_DIM];

        // gather previous h: dual parallel tagged polls (no nanosleep)
        const unsigned expect = (unsigned)(s - 1);
        const unsigned long long* src = HX[p];
        unsigned long long v0 = ld_cg64(src + tid);
        unsigned long long v1 = ld_cg64(src + tid + 256);
        while (((unsigned)(v0 >> 32) != expect) ||
               ((unsigned)(v1 >> 32) != expect)) {
            if ((unsigned)(v0 >> 32) != expect) v0 = ld_cg64(src + tid);
            if ((unsigned)(v1 >> 32) != expect) v1 = ld_cg64(src + tid + 256);
        }
        sh_h[p][tid]       = __uint_as_float((unsigned)v0);
        sh_h[p][tid + 256] = __uint_as_float((unsigned)v1);
        __syncthreads();

        // h @ W_hh^T for this warp's 4 gates
        float a0 = 0.f, a1 = 0.f, a2 = 0.f, a3 = 0.f;
#pragma unroll
        for (int u = 0; u < 16; u++) {
            float hv = sh_h[p][lane + 32 * u];
            a0 = fmaf(w0[u], hv, a0);
            a1 = fmaf(w1[u], hv, a1);
            a2 = fmaf(w2[u], hv, a2);
            a3 = fmaf(w3[u], hv, a3);
        }
#pragma unroll
        for (int off = 16; off; off >>= 1) {
            a0 += __shfl_xor_sync(0xffffffffu, a0, off);
            a1 += __shfl_xor_sync(0xffffffffu, a1, off);
            a2 += __shfl_xor_sync(0xffffffffu, a2, off);
            a3 += __shfl_xor_sync(0xffffffffu, a3, off);
        }
        float ii = fsig(pi + a0);
        float ff = fsig(pf + a1);
        float cc = ftanh_(pg + a2);
        float oo = fsig(po + a3);
        c = ff * c + ii * cc;
        float h = oo * ftanh_(c);

        if (lane == 0) {
            // publish first (critical path), then archive
            unsigned long long pk =
                ((unsigned long long)(unsigned)s << 32) |
                (unsigned long long)__float_as_uint(h);
            st_cg64(&HX[s & 1][j], pk);
            Hout[(size_t)t * D2 + d * H_DIM + j] = h;
        }
        // no trailing barrier: sh_h parity + lockstep exchange protocol
        // guarantee no warp can be 2 steps ahead of any other CTA/warp.
    }
}

// ---------------- features: feats = H1 @ lin_w^T + lin_b; expF = exp(f - rowmax) ----
__global__ __launch_bounds__(512) void feats_kernel(
    const float* __restrict__ lin_w, const float* __restrict__ lin_b)
{
    int t = blockIdx.x;
    int tid = threadIdx.x;
    int warp = tid >> 5, lane = tid & 31;
    __shared__ float sh[D2];
    __shared__ float pb[KK];
    __shared__ float mxs;
    for (int i = tid; i < D2; i += 512) sh[i] = g_H1[(size_t)t * D2 + i];
    __syncthreads();
#pragma unroll
    for (int q = 0; q < 3; q++) {
        int j = warp * 3 + q;   // 16 warps * 3 = 48
        float acc = 0.f;
        for (int k = lane; k < D2; k += 32)
            acc = fmaf(sh[k], lin_w[(size_t)j * D2 + k], acc);
#pragma unroll
        for (int off = 16; off; off >>= 1)
            acc += __shfl_xor_sync(0xffffffffu, acc, off);
        if (lane == 0) pb[j] = acc + lin_b[j];
    }
    __syncthreads();
    if (tid < 16) {
        float m = fmaxf(pb[tid], fmaxf(pb[tid + 16], pb[tid + 32]));
#pragma unroll
        for (int off = 8; off; off >>= 1)
            m = fmaxf(m, __shfl_xor_sync(0xffffu, m, off));
        if (tid == 0) { mxs = m; g_rowmax[t] = m; }
    }
    __syncthreads();
    if (tid < KK) {
        float f = pb[tid];
        g_feats[t * KK + tid] = f;
        g_expF[t * KK + tid]  = expf(f - mxs);
    }
}

// ---------------- gold score (+ rowmax sum), double precision ----------------
__global__ void score_kernel(const int* __restrict__ tags,
                             const float* __restrict__ trans)
{
    __shared__ double red[256];
    int tid = threadIdx.x;
    double part = 0.0, rm = 0.0;
    for (int s = tid; s < T_LEN; s += 256) {
        int prev = (s == 0) ? START_T : tags[s - 1];
        int cur  = tags[s];
        part += (double)trans[cur * KK + prev] + (double)g_feats[s * KK + cur];
        rm   += (double)g_rowmax[s];
    }
    red[tid] = part;
    __syncthreads();
    for (int off = 128; off; off >>= 1) {
        if (tid < off) red[tid] += red[tid + off];
        __syncthreads();
    }
    if (tid == 0)
        g_score = red[0] + (double)trans[END_T * KK + tags[T_LEN - 1]];
    __syncthreads();
    red[tid] = rm;
    __syncthreads();
    for (int off = 128; off; off >>= 1) {
        if (tid < off) red[tid] += red[tid + off];
        __syncthreads();
    }
    if (tid == 0) g_rmsum = red[0];
}

// ---------------- CRF forward scan (probability domain, single block) ----------
__global__ __launch_bounds__(192) void crf_kernel(
    const float* __restrict__ trans,
    const int* __restrict__ seq_len,
    float* __restrict__ out)
{
    __shared__ float E[KK * KK];
    __shared__ float a[KK];
    __shared__ float pb[KK];
    __shared__ float red[4][KK];
    __shared__ float scale_s;
    int tid = threadIdx.x;
    int j = tid % KK, grp = tid / KK;           // 4 groups x 48
    for (int idx = tid; idx < KK * KK; idx += 192) E[idx] = expf(trans[idx]);
    if (tid < KK) a[tid] = (tid == START_T) ? 1.f : 0.f;
    __syncthreads();

    double C = 0.0;
    for (int t = 0; t < T_LEN; t++) {
        float ef = (grp == 0) ? g_expF[t * KK + j] : 0.f;
        float part = 0.f;
        int base = grp * 12;
#pragma unroll
        for (int ii = 0; ii < 12; ii++)
            part = fmaf(a[base + ii], E[j * KK + base + ii], part);
        red[grp][j] = part;
        __syncthreads();
        if (grp == 0)
            pb[j] = (red[0][j] + red[1][j] + red[2][j] + red[3][j]) * ef;
        __syncthreads();
        if (tid < 16) {
            float m = fmaxf(pb[tid], fmaxf(pb[tid + 16], pb[tid + 32]));
#pragma unroll
            for (int off = 8; off; off >>= 1)
                m = fmaxf(m, __shfl_xor_sync(0xffffu, m, off));
            if (tid == 0) { scale_s = 1.f / m; C += (double)logf(m); }
        }
        __syncthreads();
        if (tid < KK) a[tid] = pb[tid] * scale_s;
        __syncthreads();
    }
    if (tid == 0) {
        double z = 0.0;
        for (int q = 0; q < KK; q++)
            z += (double)a[q] * exp((double)trans[END_T * KK + q]);
        double logZ = C + log(z) + g_rmsum;
        out[0] = (float)((logZ - g_score) / (double)seq_len[0]);
    }
}

// ---------------- launch ----------------
extern "C" void kernel_launch(void* const* d_in, const int* in_sizes, int n_in,
                              void* d_out, int out_size) {
    const int*   tokens     = (const int*)d_in[0];
    const int*   tags       = (const int*)d_in[1];
    const int*   seqlen     = (const int*)d_in[2];
    const float* embed      = (const float*)d_in[3];
    const float* w_ih_l0_f  = (const float*)d_in[4];
    const float* w_hh_l0_f  = (const float*)d_in[5];
    const float* b_ih_l0_f  = (const float*)d_in[6];
    const float* b_hh_l0_f  = (const float*)d_in[7];
    const float* w_ih_l0_b  = (const float*)d_in[8];
    const float* w_hh_l0_b  = (const float*)d_in[9];
    const float* b_ih_l0_b  = (const float*)d_in[10];
    const float* b_hh_l0_b  = (const float*)d_in[11];
    const float* w_ih_l1_f  = (const float*)d_in[12];
    const float* w_hh_l1_f  = (const float*)d_in[13];
    const float* b_ih_l1_f  = (const float*)d_in[14];
    const float* b_hh_l1_f  = (const float*)d_in[15];
    const float* w_ih_l1_b  = (const float*)d_in[16];
    const float* w_hh_l1_b  = (const float*)d_in[17];
    const float* b_ih_l1_b  = (const float*)d_in[18];
    const float* b_hh_l1_b  = (const float*)d_in[19];
    const float* lin_w      = (const float*)d_in[20];
    const float* lin_b      = (const float*)d_in[21];
    const float* trans      = (const float*)d_in[22];
    float* out = (float*)d_out;

    reset_kernel<<<8, 256>>>();
    gather_kernel<<<T_LEN, E_DIM>>>(tokens, embed);

    dim3 g16(G4 / GBN, T_LEN / GBM);
    // layer 0 input preactivations (Kd = E)
    gemm_nt<<<g16, 256>>>(0, w_ih_l0_f, b_ih_l0_f, b_hh_l0_f, 0, T_LEN, G4, E_DIM);
    gemm_nt<<<g16, 256>>>(0, w_ih_l0_b, b_ih_l0_b, b_hh_l0_b, 1, T_LEN, G4, E_DIM);
    lstm_rec<<<128, 256>>>(w_hh_l0_f, w_hh_l0_b, 0);

    // layer 1 input preactivations (Kd = 2H)
    gemm_nt<<<g16, 256>>>(1, w_ih_l1_f, b_ih_l1_f, b_hh_l1_f, 0, T_LEN, G4, D2);
    gemm_nt<<<g16, 256>>>(1, w_ih_l1_b, b_ih_l1_b, b_hh_l1_b, 1, T_LEN, G4, D2);
    lstm_rec<<<128, 256>>>(w_hh_l1_f, w_hh_l1_b, 1);

    feats_kernel<<<T_LEN, 512>>>(lin_w, lin_b);
    score_kernel<<<1, 256>>>(tags, trans);
    crf_kernel<<<1, 192>>>(trans, seqlen, out);
}

// round 9
// speedup vs baseline: 2.0216x; 1.8469x over previous
#include <cuda_runtime.h>
#include <cstdint>

#define T_LEN 2048
#define E_DIM 256
#define H_DIM 512
#define G4    2048   // 4*H
#define D2    1024   // 2*H
#define KK    48
#define START_T 45
#define END_T   46

// ---------------- device scratch (no allocation; __device__ globals) ----------------
__device__ __align__(128) float g_x[(size_t)T_LEN * E_DIM];        // embedded input
__device__ __align__(128) float g_G0[(size_t)T_LEN * G4];          // gate preacts, fwd dir
__device__ __align__(128) float g_G1[(size_t)T_LEN * G4];          // gate preacts, bwd dir
__device__ __align__(128) float g_H0[(size_t)T_LEN * D2];          // layer-0 output [t][fwd|bwd]
__device__ __align__(128) float g_H1[(size_t)T_LEN * D2];          // layer-1 output
__device__ __align__(128) unsigned long long g_Hx[2][2][2][H_DIM]; // [layer][dir][parity][slot]
__device__ __align__(128) float g_feats[T_LEN * KK];
__device__ __align__(128) float g_expF[T_LEN * KK];
__device__ float  g_rowmax[T_LEN];
__device__ double g_score;
__device__ double g_rmsum;

// ---------------- helpers ----------------
__device__ __forceinline__ void st_cg64(unsigned long long* p, unsigned long long v) {
    asm volatile("st.global.cg.b64 [%0], %1;" :: "l"(p), "l"(v) : "memory");
}
__device__ __forceinline__ ulonglong2 ld_cg128(const ulonglong2* p) {
    ulonglong2 v;
    asm volatile("ld.global.cg.v2.b64 {%0,%1}, [%2];"
                 : "=l"(v.x), "=l"(v.y) : "l"(p) : "memory");
    return v;
}

// Fast branch-free activations (MUFU ex2/rcp based, rel err ~1e-6).
__device__ __forceinline__ float fsig(float x) {
    float t = __expf(-x);
    return __fdividef(1.f, 1.f + t);
}
__device__ __forceinline__ float ftanh_(float x) {
    x = fminf(fmaxf(x, -15.f), 15.f);   // avoid inf/inf
    float t = __expf(2.f * x);
    return __fdividef(t - 1.f, t + 1.f);
}

// ---------------- reset exchange buffers (tag=0, value=0.0f) ----------------
__global__ void reset_kernel() {
    unsigned long long* p = &g_Hx[0][0][0][0];
    int i = blockIdx.x * blockDim.x + threadIdx.x;   // 8 blocks * 256 = 2048
    p[i] = 0ull;
    p[i + 2048] = 0ull;
}

// ---------------- embedding gather ----------------
__global__ void gather_kernel(const int* __restrict__ tokens,
                              const float* __restrict__ embed) {
    int t = blockIdx.x;
    g_x[(size_t)t * E_DIM + threadIdx.x] =
        embed[(size_t)tokens[t] * E_DIM + threadIdx.x];
}

// ---------------- fp32 NT GEMM, both directions in one launch (blockIdx.z) ----
// C[m][n] = sum_k A[m][k]*B[n][k] + b1[n] + b2[n]
// A selected by asel (0: g_x, 1: g_H0); dir z: B/biases/C selected per z.
#define GBM 128
#define GBN 128
#define GBK 8
__global__ __launch_bounds__(256, 2) void gemm_nt2(
    int asel,
    const float* __restrict__ Bf, const float* __restrict__ Bb,
    const float* __restrict__ b1f, const float* __restrict__ b2f,
    const float* __restrict__ b1b, const float* __restrict__ b2b,
    int M, int N, int Kd)
{
    const int z = blockIdx.z;
    const float* A     = asel ? g_H0 : g_x;
    const float* B     = z ? Bb  : Bf;
    const float* bias1 = z ? b1b : b1f;
    const float* bias2 = z ? b2b : b2f;
    float* C           = z ? g_G1 : g_G0;

    __shared__ float As[GBK][GBM];
    __shared__ float Bs[GBK][GBN];
    int tid = threadIdx.x;
    int m0 = blockIdx.y * GBM, n0 = blockIdx.x * GBN;
    int tx = tid & 15, ty = tid >> 4;     // 16x16 threads, 8x8 microtile each
    int lr = tid >> 1;                    // 0..127 row of tile
    int lc = (tid & 1) * 4;               // 0 or 4 within BK

    float acc[8][8];
#pragma unroll
    for (int i = 0; i < 8; i++)
#pragma unroll
        for (int jj = 0; jj < 8; jj++) acc[i][jj] = 0.f;

    const float* Ap = A + (size_t)(m0 + lr) * Kd + lc;
    const float* Bp = B + (size_t)(n0 + lr) * Kd + lc;

    for (int k0 = 0; k0 < Kd; k0 += GBK) {
        float4 av = *(const float4*)(Ap + k0);
        float4 bv = *(const float4*)(Bp + k0);
        __syncthreads();
        As[lc + 0][lr] = av.x; As[lc + 1][lr] = av.y;
        As[lc + 2][lr] = av.z; As[lc + 3][lr] = av.w;
        Bs[lc + 0][lr] = bv.x; Bs[lc + 1][lr] = bv.y;
        Bs[lc + 2][lr] = bv.z; Bs[lc + 3][lr] = bv.w;
        __syncthreads();
#pragma unroll
        for (int k = 0; k < GBK; k++) {
            float ar[8], br[8];
#pragma unroll
            for (int i = 0; i < 8; i++)  ar[i]  = As[k][ty * 8 + i];
#pragma unroll
            for (int jj = 0; jj < 8; jj++) br[jj] = Bs[k][tx * 8 + jj];
#pragma unroll
            for (int i = 0; i < 8; i++)
#pragma unroll
                for (int jj = 0; jj < 8; jj++)
                    acc[i][jj] = fmaf(ar[i], br[jj], acc[i][jj]);
        }
    }
#pragma unroll
    for (int i = 0; i < 8; i++) {
        size_t m = (size_t)(m0 + ty * 8 + i);
#pragma unroll
        for (int jj = 0; jj < 8; jj++) {
            int n = n0 + tx * 8 + jj;
            C[m * N + n] = acc[i][jj] + bias1[n] + bias2[n];
        }
    }
}

// ---------------- persistent recurrent LSTM step kernel ----------------
// 128 CTAs: blockIdx/64 = direction, 8 warps/CTA, each warp owns one h output j.
// W_hh rows (i,f,g,o for j) live in registers: 4x16 floats per lane.
// h exchange: tagged 64-bit words in L2, parity double-buffered by step.
// Poll: one ld.cg.v2.b64 per thread (2 tagged words), unconditional reload.
__global__ __launch_bounds__(256, 1) void lstm_rec(
    const float* __restrict__ Wf, const float* __restrict__ Wb, int layer)
{
    const int d    = blockIdx.x >> 6;
    const int b    = blockIdx.x & 63;
    const int tid  = threadIdx.x;
    const int warp = tid >> 5, lane = tid & 31;
    const int j    = b * 8 + warp;

    const float* G = d ? g_G1 : g_G0;
    const float* W = d ? Wb : Wf;
    float* Hout    = layer ? g_H1 : g_H0;
    unsigned long long (*HX)[H_DIM] = g_Hx[layer][d];

    __shared__ float sh_h[2][H_DIM];

    float w0[16], w1[16], w2[16], w3[16];
#pragma unroll
    for (int u = 0; u < 16; u++) {
        int k = lane + 32 * u;
        w0[u] = W[(size_t)(0 * H_DIM + j) * H_DIM + k];
        w1[u] = W[(size_t)(1 * H_DIM + j) * H_DIM + k];
        w2[u] = W[(size_t)(2 * H_DIM + j) * H_DIM + k];
        w3[u] = W[(size_t)(3 * H_DIM + j) * H_DIM + k];
    }
    float c = 0.f;

    for (int s = 1; s <= T_LEN; s++) {
        const int t = d ? (T_LEN - s) : (s - 1);
        const int p = (s - 1) & 1;
        const float* Gp = G + (size_t)t * G4 + j;
        // issue G-preact loads early; they complete during the poll
        float pi = Gp[0];
        float pf = Gp[H_DIM];
        float pg = Gp[2 * H_DIM];
        float po = Gp[3 * H_DIM];

        // gather previous h: single v2 tagged poll (2 words/thread)
        const unsigned expect = (unsigned)(s - 1);
        const ulonglong2* src = (const ulonglong2*)HX[p];
        ulonglong2 v = ld_cg128(src + tid);
        while (((unsigned)(v.x >> 32) != expect) |
               ((unsigned)(v.y >> 32) != expect)) {
            v = ld_cg128(src + tid);
        }
        *(float2*)&sh_h[p][2 * tid] =
            make_float2(__uint_as_float((unsigned)v.x),
                        __uint_as_float((unsigned)v.y));
        __syncthreads();

        // h @ W_hh^T for this warp's 4 gates
        float a0 = 0.f, a1 = 0.f, a2 = 0.f, a3 = 0.f;
#pragma unroll
        for (int u = 0; u < 16; u++) {
            float hv = sh_h[p][lane + 32 * u];
            a0 = fmaf(w0[u], hv, a0);
            a1 = fmaf(w1[u], hv, a1);
            a2 = fmaf(w2[u], hv, a2);
            a3 = fmaf(w3[u], hv, a3);
        }
#pragma unroll
        for (int off = 16; off; off >>= 1) {
            a0 += __shfl_xor_sync(0xffffffffu, a0, off);
            a1 += __shfl_xor_sync(0xffffffffu, a1, off);
            a2 += __shfl_xor_sync(0xffffffffu, a2, off);
            a3 += __shfl_xor_sync(0xffffffffu, a3, off);
        }
        float ii = fsig(pi + a0);
        float ff = fsig(pf + a1);
        float cc = ftanh_(pg + a2);
        float oo = fsig(po + a3);
        c = ff * c + ii * cc;
        float h = oo * ftanh_(c);

        if (lane == 0) {
            // publish first (critical path), then archive
            unsigned long long pk =
                ((unsigned long long)(unsigned)s << 32) |
                (unsigned long long)__float_as_uint(h);
            st_cg64(&HX[s & 1][j], pk);
            Hout[(size_t)t * D2 + d * H_DIM + j] = h;
        }
        // no trailing barrier: sh_h parity + lockstep exchange protocol
        // guarantee no warp can be 2 steps ahead of any other CTA/warp.
    }
}

// ---------------- features: feats = H1 @ lin_w^T + lin_b; expF = exp(f - rowmax) ----
__global__ __launch_bounds__(512) void feats_kernel(
    const float* __restrict__ lin_w, const float* __restrict__ lin_b)
{
    int t = blockIdx.x;
    int tid = threadIdx.x;
    int warp = tid >> 5, lane = tid & 31;
    __shared__ float sh[D2];
    __shared__ float pb[KK];
    __shared__ float mxs;
    for (int i = tid; i < D2; i += 512) sh[i] = g_H1[(size_t)t * D2 + i];
    __syncthreads();
#pragma unroll
    for (int q = 0; q < 3; q++) {
        int j = warp * 3 + q;   // 16 warps * 3 = 48
        float acc = 0.f;
        for (int k = lane; k < D2; k += 32)
            acc = fmaf(sh[k], lin_w[(size_t)j * D2 + k], acc);
#pragma unroll
        for (int off = 16; off; off >>= 1)
            acc += __shfl_xor_sync(0xffffffffu, acc, off);
        if (lane == 0) pb[j] = acc + lin_b[j];
    }
    __syncthreads();
    if (tid < 16) {
        float m = fmaxf(pb[tid], fmaxf(pb[tid + 16], pb[tid + 32]));
#pragma unroll
        for (int off = 8; off; off >>= 1)
            m = fmaxf(m, __shfl_xor_sync(0xffffu, m, off));
        if (tid == 0) { mxs = m; g_rowmax[t] = m; }
    }
    __syncthreads();
    if (tid < KK) {
        float f = pb[tid];
        g_feats[t * KK + tid] = f;
        g_expF[t * KK + tid]  = expf(f - mxs);
    }
}

// ---------------- gold score (+ rowmax sum), double precision ----------------
__global__ void score_kernel(const int* __restrict__ tags,
                             const float* __restrict__ trans)
{
    __shared__ double red[256];
    int tid = threadIdx.x;
    double part = 0.0, rm = 0.0;
    for (int s = tid; s < T_LEN; s += 256) {
        int prev = (s == 0) ? START_T : tags[s - 1];
        int cur  = tags[s];
        part += (double)trans[cur * KK + prev] + (double)g_feats[s * KK + cur];
        rm   += (double)g_rowmax[s];
    }
    red[tid] = part;
    __syncthreads();
    for (int off = 128; off; off >>= 1) {
        if (tid < off) red[tid] += red[tid + off];
        __syncthreads();
    }
    if (tid == 0)
        g_score = red[0] + (double)trans[END_T * KK + tags[T_LEN - 1]];
    __syncthreads();
    red[tid] = rm;
    __syncthreads();
    for (int off = 128; off; off >>= 1) {
        if (tid < off) red[tid] += red[tid + off];
        __syncthreads();
    }
    if (tid == 0) g_rmsum = red[0];
}

// ---------------- CRF forward scan: 64 threads, E rows in registers ----------
// prob domain, renorm every 4 steps, expF prefetched one step ahead,
// one barrier per step (double-buffered alpha).
__global__ __launch_bounds__(64) void crf_kernel(
    const float* __restrict__ trans,
    const int* __restrict__ seq_len,
    float* __restrict__ out)
{
    const int j = threadIdx.x;        // 0..63; j>=48 are zero-lanes
    const bool act = (j < KK);
    const int wid = j >> 5;

    __shared__ float a[2][64];
    __shared__ float wmax[2];
    __shared__ float zterms[64];

    float E[KK];
#pragma unroll
    for (int i = 0; i < KK; i++)
        E[i] = act ? expf(trans[j * KK + i]) : 0.f;

    a[0][j] = (j == START_T) ? 1.f : 0.f;
    a[1][j] = 0.f;
    __syncthreads();

    double C = 0.0;                    // valid on thread 0 only
    float ef = act ? g_expF[j] : 0.f;  // expF[t=0]

    for (int t = 0; t < T_LEN; t++) {
        // prefetch next step's emission factor (hides L2 latency)
        float ef_next = (act && t + 1 < T_LEN) ? g_expF[(t + 1) * KK + j] : 0.f;

        const float* pa = a[t & 1];
        float s0 = 0.f, s1 = 0.f, s2 = 0.f, s3 = 0.f;
#pragma unroll
        for (int i = 0; i < 12; i++) {
            s0 = fmaf(pa[i],      E[i],      s0);
            s1 = fmaf(pa[i + 12], E[i + 12], s1);
            s2 = fmaf(pa[i + 24], E[i + 24], s2);
            s3 = fmaf(pa[i + 36], E[i + 36], s3);
        }
        float val = ((s0 + s1) + (s2 + s3)) * ef;

        if ((t & 3) == 3) {
            // max-renormalize (values are >= 0; at least one > 0)
            float m = val;
#pragma unroll
            for (int off = 16; off; off >>= 1)
                m = fmaxf(m, __shfl_xor_sync(0xffffffffu, m, off));
            if ((j & 31) == 0) wmax[wid] = m;
            __syncthreads();
            m = fmaxf(wmax[0], wmax[1]);
            if (j == 0) C += (double)logf(m);
            val *= (1.f / m);
        }
        a[(t + 1) & 1][j] = val;
        ef = ef_next;
        __syncthreads();
    }

    // tail: z = sum_j alpha[j] * exp(trans[END][j])
    float fa = a[0][j];   // T_LEN even -> final buffer is a[0]
    zterms[j] = act ? fa * expf(trans[END_T * KK + j]) : 0.f;
    __syncthreads();
    if (j == 0) {
        double z = 0.0;
        for (int q = 0; q < KK; q++) z += (double)zterms[q];
        double logZ = C + log(z) + g_rmsum;
        out[0] = (float)((logZ - g_score) / (double)seq_len[0]);
    }
}

// ---------------- launch ----------------
extern "C" void kernel_launch(void* const* d_in, const int* in_sizes, int n_in,
                              void* d_out, int out_size) {
    const int*   tokens     = (const int*)d_in[0];
    const int*   tags       = (const int*)d_in[1];
    const int*   seqlen     = (const int*)d_in[2];
    const float* embed      = (const float*)d_in[3];
    const float* w_ih_l0_f  = (const float*)d_in[4];
    const float* w_hh_l0_f  = (const float*)d_in[5];
    const float* b_ih_l0_f  = (const float*)d_in[6];
    const float* b_hh_l0_f  = (const float*)d_in[7];
    const float* w_ih_l0_b  = (const float*)d_in[8];
    const float* w_hh_l0_b  = (const float*)d_in[9];
    const float* b_ih_l0_b  = (const float*)d_in[10];
    const float* b_hh_l0_b  = (const float*)d_in[11];
    const float* w_ih_l1_f  = (const float*)d_in[12];
    const float* w_hh_l1_f  = (const float*)d_in[13];
    const float* b_ih_l1_f  = (const float*)d_in[14];
    const float* b_hh_l1_f  = (const float*)d_in[15];
    const float* w_ih_l1_b  = (const float*)d_in[16];
    const float* w_hh_l1_b  = (const float*)d_in[17];
    const float* b_ih_l1_b  = (const float*)d_in[18];
    const float* b_hh_l1_b  = (const float*)d_in[19];
    const float* lin_w      = (const float*)d_in[20];
    const float* lin_b      = (const float*)d_in[21];
    const float* trans      = (const float*)d_in[22];
    float* out = (float*)d_out;

    reset_kernel<<<8, 256>>>();                                   // launch 1
    gather_kernel<<<T_LEN, E_DIM>>>(tokens, embed);               // launch 2

    dim3 g2(G4 / GBN, T_LEN / GBM, 2);
    // layer 0: both directions in one launch (Kd = E)
    gemm_nt2<<<g2, 256>>>(0, w_ih_l0_f, w_ih_l0_b,                // launch 3
                          b_ih_l0_f, b_hh_l0_f, b_ih_l0_b, b_hh_l0_b,
                          T_LEN, G4, E_DIM);
    lstm_rec<<<128, 256>>>(w_hh_l0_f, w_hh_l0_b, 0);              // launch 4

    // layer 1: both directions in one launch (Kd = 2H)
    gemm_nt2<<<g2, 256>>>(1, w_ih_l1_f, w_ih_l1_b,                // launch 5
                          b_ih_l1_f, b_hh_l1_f, b_ih_l1_b, b_hh_l1_b,
                          T_LEN, G4, D2);
    lstm_rec<<<128, 256>>>(w_hh_l1_f, w_hh_l1_b, 1);              // launch 6 (profiled)

    feats_kernel<<<T_LEN, 512>>>(lin_w, lin_b);                   // launch 7
    score_kernel<<<1, 256>>>(tags, trans);                        // launch 8
    crf_kernel<<<1, 64>>>(trans, seqlen, out);                    // launch 9
}